// round 7
// baseline (speedup 1.0000x reference)
#include <cuda_runtime.h>
#include <cstdint>

#define KVOL 27
#define MAXN 131072
#define TILE_M 128

// ---------------------------------------------------------------------------
// Scratch (device globals — allocation rules forbid cudaMalloc)
// ---------------------------------------------------------------------------
__device__ static int   g_nbr[KVOL * MAXN];               // nbr[k][o] = in idx or -1
__device__ __align__(16) static float g_wt[KVOL * 1024];  // Wt[k][o][i], tf32-rounded
__device__ static float g_sum[32];
__device__ static float g_sumsq[32];

// ---------------------------------------------------------------------------
// cp.async helpers (Ampere+; legal under compute_100)
// ---------------------------------------------------------------------------
__device__ __forceinline__ uint32_t smem_u32(const void* p) {
    uint32_t a;
    asm("{ .reg .u64 t; cvta.to.shared.u64 t, %1; cvt.u32.u64 %0, t; }"
        : "=r"(a) : "l"(p));
    return a;
}
// 16B async copy; src_sz = 16 copies, src_sz = 0 writes zeros (no read)
__device__ __forceinline__ void cp_async16(uint32_t dst, const void* src, int src_sz) {
    asm volatile("cp.async.ca.shared.global [%0], [%1], 16, %2;"
                 :: "r"(dst), "l"(src), "r"(src_sz) : "memory");
}
#define CP_COMMIT() asm volatile("cp.async.commit_group;" ::: "memory")
#define CP_WAIT0()  asm volatile("cp.async.wait_group 0;" ::: "memory")
#define CP_WAIT1()  asm volatile("cp.async.wait_group 1;" ::: "memory")

// ---------------------------------------------------------------------------
// K1: init nbr table to -1, zero channel sums
// ---------------------------------------------------------------------------
__global__ void k_init(int total) {
    int idx = blockIdx.x * blockDim.x + threadIdx.x;
    int stride = gridDim.x * blockDim.x;
    for (int j = idx; j < total; j += stride) g_nbr[j] = -1;
    if (idx < 32) { g_sum[idx] = 0.f; g_sumsq[idx] = 0.f; }
}

// ---------------------------------------------------------------------------
// K2: scatter kernel maps -> dense nbr table (validity from out_idx
// monotonicity: valid entries form a strictly increasing prefix per k).
// ---------------------------------------------------------------------------
__global__ void k_scatter(const int* __restrict__ out_idx,
                          const int* __restrict__ in_idx, int N) {
    int p = blockIdx.x * blockDim.x + threadIdx.x;
    int k = blockIdx.y;
    if (p >= N) return;
    long long base = (long long)k * N;
    int o = out_idx[base + p];
    bool valid = (p == 0) || (o > out_idx[base + p - 1]);
    if (valid) g_nbr[base + o] = in_idx[base + p];
}

// ---------------------------------------------------------------------------
// K2b: W[k][i][o] -> Wt[k][o][i], rounded to tf32 (rna). Plain layout (the
// conv kernel reads B fragments straight from global; W stays L1-resident).
// ---------------------------------------------------------------------------
__global__ void k_wt(const float* __restrict__ W) {
    int k = blockIdx.x;
    for (int j = threadIdx.x; j < 1024; j += blockDim.x) {
        int o = j >> 5, i = j & 31;
        float v = W[k * 1024 + i * 32 + o];
        uint32_t t;
        asm("cvt.rna.tf32.f32 %0, %1;" : "=r"(t) : "f"(v));
        g_wt[k * 1024 + o * 32 + i] = __uint_as_float(t);
    }
}

// ---------------------------------------------------------------------------
// A-fragment load from warp-private XOR-swizzled smem tile (16 rows x 32 f).
// Group gq of local row r lives at group gq ^ (r & 7)  -> conflict-free.
// ---------------------------------------------------------------------------
__device__ __forceinline__ uint32_t ld_a(const float* a_s, int r, int col) {
    int phys = ((((col >> 2) ^ r) & 7) << 2) | (col & 3);
    float v = a_s[(r << 5) + phys];
    uint32_t t;
    asm("cvt.rna.tf32.f32 %0, %1;" : "=r"(t) : "f"(v));
    return t;
}

// ---------------------------------------------------------------------------
// K3: warp-private pipelined mma.sync tf32 gather-GEMM.
// One CTA / 128-voxel tile, 8 warps; warp w owns rows [w*16, w*16+16) and
// runs its own 27-stage pipeline: idx prefetched 2 stages ahead (registers),
// A data 1 stage ahead (cp.async, per-warp double buffer). ZERO __syncthreads
// in the main loop; W fragments read directly from global (L1-resident).
// ---------------------------------------------------------------------------
__global__ __launch_bounds__(256, 2) void k_conv_mma(const float* __restrict__ feats,
                                                     float* __restrict__ out, int N) {
    __shared__ __align__(16) float a_ws[8][2][16 * 32];  // 32768 B
    __shared__ float s_red[2 * 8 * 32];                  //  2048 B
    const int tid  = threadIdx.x;
    const int w    = tid >> 5;
    const int lane = tid & 31;
    const int g    = lane >> 2;
    const int q    = lane & 3;
    const int gq   = lane & 7;           // gather group
    const int obase = blockIdx.x * TILE_M;
    const int v0g   = obase + w * 16;    // warp's global row base

    // this thread's 4 gather rows (local 0..15) and swizzled dst addresses
    int rr[4];
    uint32_t adst[2][4];
    #pragma unroll
    for (int t = 0; t < 4; ++t) {
        rr[t] = (lane >> 3) + 4 * t;
        #pragma unroll
        for (int b = 0; b < 2; ++b)
            adst[b][t] = smem_u32(&a_ws[w][b][(rr[t] << 5) + ((gq ^ (rr[t] & 7)) << 2)]);
    }

    float c_[4][4];
    #pragma unroll
    for (int nt = 0; nt < 4; ++nt)
        c_[nt][0] = c_[nt][1] = c_[nt][2] = c_[nt][3] = 0.f;

    // load indices for stage k into a register quad (guarded for tail tile)
    auto ld_idx = [&](int k, int (&idx)[4]) {
        const int* nb = g_nbr + (long long)k * N + v0g;
        #pragma unroll
        for (int t = 0; t < 4; ++t) {
            int val = nb[rr[t]];
            idx[t] = (v0g + rr[t] < N) ? val : -1;
        }
    };
    // issue A gather for stage k into buffer b using prefetched indices
    auto issue_data = [&](int b, const int (&idx)[4]) {
        #pragma unroll
        for (int t = 0; t < 4; ++t) {
            int src = idx[t];
            const float* gp = feats + (src >= 0 ? (long long)src * 32 + gq * 4 : 0);
            cp_async16(adst[b][t], gp, src >= 0 ? 16 : 0);
        }
        CP_COMMIT();
    };
    // consume stage k from buffer b
    auto compute = [&](int k, int b) {
        const float* ap = a_ws[w][b];
        const float* wk = g_wt + k * 1024;
        #pragma unroll
        for (int ks = 0; ks < 4; ++ks) {
            int col0 = ks * 8 + q, col1 = col0 + 4;
            uint32_t a0 = ld_a(ap, g, col0);
            uint32_t a1 = ld_a(ap, g + 8, col0);
            uint32_t a2 = ld_a(ap, g, col1);
            uint32_t a3 = ld_a(ap, g + 8, col1);
            #pragma unroll
            for (int nt = 0; nt < 4; ++nt) {
                int o = nt * 8 + g;
                uint32_t b0 = __float_as_uint(wk[o * 32 + col0]);
                uint32_t b1 = __float_as_uint(wk[o * 32 + col1]);
                asm volatile(
                    "mma.sync.aligned.m16n8k8.row.col.f32.tf32.tf32.f32 "
                    "{%0,%1,%2,%3}, {%4,%5,%6,%7}, {%8,%9}, {%0,%1,%2,%3};"
                    : "+f"(c_[nt][0]), "+f"(c_[nt][1]),
                      "+f"(c_[nt][2]), "+f"(c_[nt][3])
                    : "r"(a0), "r"(a1), "r"(a2), "r"(a3), "r"(b0), "r"(b1));
            }
        }
    };
    // one pipeline step: prefetch idx(k+2), land data(k), compute(k), issue data(k+2)
    auto body = [&](int k, int b, int (&idx)[4]) {
        if (k + 2 < KVOL) ld_idx(k + 2, idx);   // overwrite idx(k): already consumed
        if (k < KVOL - 1) CP_WAIT1(); else CP_WAIT0();
        __syncwarp();
        compute(k, b);
        if (k + 2 < KVOL) issue_data(b, idx);   // reuse buffer b (stage k read done)
    };

    int idx0[4], idx1[4];
    ld_idx(0, idx0); issue_data(0, idx0);       // prolog: stages 0 and 1 in flight
    ld_idx(1, idx1); issue_data(1, idx1);

    #pragma unroll 1
    for (int k = 0; k < KVOL - 1; k += 2) {
        body(k, 0, idx0);
        body(k + 1, 1, idx1);
    }
    body(KVOL - 1, 0, idx0);                    // k = 26 (even)

    // ---- epilogue: store pre-BN rows -------------------------------------
    int r0g = v0g + g;
    int r1g = r0g + 8;
    #pragma unroll
    for (int nt = 0; nt < 4; ++nt) {
        if (r0g < N)
            *(float2*)(out + (long long)r0g * 32 + nt * 8 + 2 * q) =
                make_float2(c_[nt][0], c_[nt][1]);
        if (r1g < N)
            *(float2*)(out + (long long)r1g * 32 + nt * 8 + 2 * q) =
                make_float2(c_[nt][2], c_[nt][3]);
    }

    // ---- BN sums (padding rows are exactly zero, safe to include) --------
    float s[8], sq[8];
    #pragma unroll
    for (int nt = 0; nt < 4; ++nt) {
        s[nt * 2 + 0] = c_[nt][0] + c_[nt][2];
        s[nt * 2 + 1] = c_[nt][1] + c_[nt][3];
        sq[nt * 2 + 0] = c_[nt][0] * c_[nt][0] + c_[nt][2] * c_[nt][2];
        sq[nt * 2 + 1] = c_[nt][1] * c_[nt][1] + c_[nt][3] * c_[nt][3];
    }
    #pragma unroll
    for (int off = 16; off >= 4; off >>= 1) {
        #pragma unroll
        for (int e = 0; e < 8; ++e) {
            s[e]  += __shfl_xor_sync(~0u, s[e], off);
            sq[e] += __shfl_xor_sync(~0u, sq[e], off);
        }
    }
    if (lane < 4) {
        #pragma unroll
        for (int nt = 0; nt < 4; ++nt) {
            int ch = nt * 8 + 2 * lane;
            s_red[w * 32 + ch]           = s[nt * 2 + 0];
            s_red[w * 32 + ch + 1]       = s[nt * 2 + 1];
            s_red[256 + w * 32 + ch]     = sq[nt * 2 + 0];
            s_red[256 + w * 32 + ch + 1] = sq[nt * 2 + 1];
        }
    }
    __syncthreads();
    if (tid < 32) {
        float ts = 0.f, tq = 0.f;
        #pragma unroll
        for (int ww = 0; ww < 8; ++ww) {
            ts += s_red[ww * 32 + tid];
            tq += s_red[256 + ww * 32 + tid];
        }
        atomicAdd(&g_sum[tid], ts);
        atomicAdd(&g_sumsq[tid], tq);
    }
}

// ---------------------------------------------------------------------------
// K4: BN (batch stats, biased var) + ReLU, in place on out
// ---------------------------------------------------------------------------
__global__ void k_bnrelu(const float* __restrict__ gamma,
                         const float* __restrict__ beta,
                         float* __restrict__ out, int N) {
    __shared__ float s_scale[32], s_shift[32];
    int tid = threadIdx.x;
    if (tid < 32) {
        float invN = 1.0f / (float)N;
        float mean = g_sum[tid] * invN;
        float var  = g_sumsq[tid] * invN - mean * mean;
        float sc   = gamma[tid] * rsqrtf(var + 1e-5f);
        s_scale[tid] = sc;
        s_shift[tid] = fmaf(-mean, sc, beta[tid]);
    }
    __syncthreads();
    long long total = (long long)N * 8;
    for (long long j = blockIdx.x * (long long)blockDim.x + tid; j < total;
         j += (long long)gridDim.x * blockDim.x) {
        int c = ((int)(j & 7)) * 4;
        float4 v = *(const float4*)(out + j * 4);
        float4 r;
        r.x = fmaxf(fmaf(v.x, s_scale[c + 0], s_shift[c + 0]), 0.f);
        r.y = fmaxf(fmaf(v.y, s_scale[c + 1], s_shift[c + 1]), 0.f);
        r.z = fmaxf(fmaf(v.z, s_scale[c + 2], s_shift[c + 2]), 0.f);
        r.w = fmaxf(fmaf(v.w, s_scale[c + 3], s_shift[c + 3]), 0.f);
        *(float4*)(out + j * 4) = r;
    }
}

// ---------------------------------------------------------------------------
// Launch. Inputs: feats, W, gamma, beta, in_idx, out_idx, mask (mask unused)
// ---------------------------------------------------------------------------
extern "C" void kernel_launch(void* const* d_in, const int* in_sizes, int n_in,
                              void* d_out, int out_size) {
    const float* feats   = (const float*)d_in[0];
    const float* W       = (const float*)d_in[1];
    const float* gamma   = (const float*)d_in[2];
    const float* beta    = (const float*)d_in[3];
    const int*   in_idx  = (const int*)d_in[4];
    const int*   out_idx = (const int*)d_in[5];
    const int N = in_sizes[0] / 32;
    float* out = (float*)d_out;

    k_init<<<1024, 256>>>(KVOL * N);
    dim3 sg((N + 255) / 256, KVOL);
    k_scatter<<<sg, 256>>>(out_idx, in_idx, N);
    k_wt<<<KVOL, 256>>>(W);
    k_conv_mma<<<(N + TILE_M - 1) / TILE_M, 256>>>(feats, out, N);
    k_bnrelu<<<1024, 256>>>(gamma, beta, out, N);
}

// round 8
// speedup vs baseline: 2.6414x; 2.6414x over previous
#include <cuda_runtime.h>
#include <cstdint>

#define KVOL 27
#define MAXN 131072
#define TILE_M 128

// ---------------------------------------------------------------------------
// Scratch (device globals — allocation rules forbid cudaMalloc)
// ---------------------------------------------------------------------------
__device__ static int   g_nbr[KVOL * MAXN];                // nbr[k][o] = in idx or -1
__device__ __align__(16) static float g_wf[KVOL * 1024];   // lane-order W fragments
__device__ __align__(16) static float g_ftf[MAXN * 32];    // feats, tf32-rounded
__device__ static float g_sum[32];
__device__ static float g_sumsq[32];

// ---------------------------------------------------------------------------
// cp.async helpers (Ampere+; legal under compute_100)
// ---------------------------------------------------------------------------
__device__ __forceinline__ uint32_t smem_u32(const void* p) {
    uint32_t a;
    asm("{ .reg .u64 t; cvta.to.shared.u64 t, %1; cvt.u32.u64 %0, t; }"
        : "=r"(a) : "l"(p));
    return a;
}
// 16B async copy; src_sz = 16 copies, src_sz = 0 writes zeros (no read)
__device__ __forceinline__ void cp_async16(uint32_t dst, const void* src, int src_sz) {
    asm volatile("cp.async.ca.shared.global [%0], [%1], 16, %2;"
                 :: "r"(dst), "l"(src), "r"(src_sz) : "memory");
}
#define CP_COMMIT() asm volatile("cp.async.commit_group;" ::: "memory")
#define CP_WAIT0()  asm volatile("cp.async.wait_group 0;" ::: "memory")
#define CP_WAIT1()  asm volatile("cp.async.wait_group 1;" ::: "memory")

// ---------------------------------------------------------------------------
// K1: init nbr table to -1, zero channel sums
// ---------------------------------------------------------------------------
__global__ void k_init(int total) {
    int idx = blockIdx.x * blockDim.x + threadIdx.x;
    int stride = gridDim.x * blockDim.x;
    for (int j = idx; j < total; j += stride) g_nbr[j] = -1;
    if (idx < 32) { g_sum[idx] = 0.f; g_sumsq[idx] = 0.f; }
}

// ---------------------------------------------------------------------------
// K2: scatter kernel maps -> dense nbr table (validity from out_idx
// monotonicity: valid entries form a strictly increasing prefix per k).
// ---------------------------------------------------------------------------
__global__ void k_scatter(const int* __restrict__ out_idx,
                          const int* __restrict__ in_idx, int N) {
    int p = blockIdx.x * blockDim.x + threadIdx.x;
    int k = blockIdx.y;
    if (p >= N) return;
    long long base = (long long)k * N;
    int o = out_idx[base + p];
    bool valid = (p == 0) || (o > out_idx[base + p - 1]);
    if (valid) g_nbr[base + o] = in_idx[base + p];
}

// ---------------------------------------------------------------------------
// K2b: build lane-order W fragments, tf32-rounded.
// Fragment value for (lane, nt, ks, sel): Wt[o][col] = W[col][o]
//   with o = nt*8 + (lane>>2), col = ks*8 + (lane&3) + sel*4.
// Stored so each float4 slot idx = nt*2 + (ks>>1) is coalesced across lanes:
//   g_wf[k*1024 + idx*128 + lane*4 + (ks&1)*2 + sel]
// ---------------------------------------------------------------------------
__global__ void k_wfrag(const float* __restrict__ W) {
    int k = blockIdx.x;
    for (int j = threadIdx.x; j < 1024; j += blockDim.x) {
        int idx  = j >> 7;          // 0..7
        int lane = (j >> 2) & 31;
        int c    = j & 3;
        int nt = idx >> 1, p = idx & 1;
        int ks = 2 * p + (c >> 1);
        int sel = c & 1;
        int g = lane >> 2, q = lane & 3;
        int o = nt * 8 + g;
        int col = ks * 8 + q + sel * 4;
        float v = W[k * 1024 + col * 32 + o];
        uint32_t t;
        asm("cvt.rna.tf32.f32 %0, %1;" : "=r"(t) : "f"(v));
        g_wf[k * 1024 + j] = __uint_as_float(t);
    }
}

// ---------------------------------------------------------------------------
// K2c: pre-round feats to tf32 (rna) so the conv inner loop has no cvt.
// ---------------------------------------------------------------------------
__global__ void k_fcvt(const float* __restrict__ feats, int total) {
    int i = blockIdx.x * blockDim.x + threadIdx.x;
    int stride = gridDim.x * blockDim.x;
    for (int j = i; j < total; j += stride) {
        uint32_t t;
        asm("cvt.rna.tf32.f32 %0, %1;" : "=r"(t) : "f"(feats[j]));
        g_ftf[j] = __uint_as_float(t);
    }
}

// ---------------------------------------------------------------------------
// A-fragment load from warp-private XOR-swizzled smem tile (16 rows x 32 f).
// Group gq of local row r lives at group gq ^ (r & 7)  -> conflict-free.
// ---------------------------------------------------------------------------
__device__ __forceinline__ uint32_t ld_a(const float* a_s, int r, int col) {
    int phys = ((((col >> 2) ^ r) & 7) << 2) | (col & 3);
    return __float_as_uint(a_s[(r << 5) + phys]);  // already tf32-rounded
}

// ---------------------------------------------------------------------------
// K3: warp-private pipelined mma.sync tf32 gather-GEMM.
// One CTA / 128-voxel tile, 8 warps; warp w owns rows [w*16, w*16+16).
// idx prefetched 2 stages ahead (registers), A data 1 stage ahead (cp.async,
// per-warp double buffer). ZERO __syncthreads in the main loop. W fragments:
// 8 fully-coalesced LDG.128 per warp-k from the lane-order table (L1-hot).
// ---------------------------------------------------------------------------
__global__ __launch_bounds__(256, 2) void k_conv_mma(float* __restrict__ out, int N) {
    __shared__ __align__(16) float a_ws[8][2][16 * 32];  // 32768 B
    __shared__ float s_red[2 * 8 * 32];                  //  2048 B
    const int tid  = threadIdx.x;
    const int w    = tid >> 5;
    const int lane = tid & 31;
    const int g    = lane >> 2;
    const int q    = lane & 3;
    const int gq   = lane & 7;           // gather group
    const int obase = blockIdx.x * TILE_M;
    const int v0g   = obase + w * 16;    // warp's global row base

    // this thread's 4 gather rows (local 0..15) and swizzled dst addresses
    int rr[4];
    uint32_t adst[2][4];
    #pragma unroll
    for (int t = 0; t < 4; ++t) {
        rr[t] = (lane >> 3) + 4 * t;
        #pragma unroll
        for (int b = 0; b < 2; ++b)
            adst[b][t] = smem_u32(&a_ws[w][b][(rr[t] << 5) + ((gq ^ (rr[t] & 7)) << 2)]);
    }

    float c_[4][4];
    #pragma unroll
    for (int nt = 0; nt < 4; ++nt)
        c_[nt][0] = c_[nt][1] = c_[nt][2] = c_[nt][3] = 0.f;

    auto ld_idx = [&](int k, int (&idx)[4]) {
        const int* nb = g_nbr + (long long)k * N + v0g;
        #pragma unroll
        for (int t = 0; t < 4; ++t) {
            int val = nb[rr[t]];
            idx[t] = (v0g + rr[t] < N) ? val : -1;
        }
    };
    auto issue_data = [&](int b, const int (&idx)[4]) {
        #pragma unroll
        for (int t = 0; t < 4; ++t) {
            int src = idx[t];
            const float* gp = g_ftf + (src >= 0 ? (long long)src * 32 + gq * 4 : 0);
            cp_async16(adst[b][t], gp, src >= 0 ? 16 : 0);
        }
        CP_COMMIT();
    };
    auto compute = [&](int k, int b) {
        const float* ap = a_ws[w][b];
        uint32_t A[4][4];
        #pragma unroll
        for (int ks = 0; ks < 4; ++ks) {
            int col0 = ks * 8 + q, col1 = col0 + 4;
            A[ks][0] = ld_a(ap, g, col0);
            A[ks][1] = ld_a(ap, g + 8, col0);
            A[ks][2] = ld_a(ap, g, col1);
            A[ks][3] = ld_a(ap, g + 8, col1);
        }
        const float4* wf = (const float4*)(g_wf + k * 1024);
        #pragma unroll
        for (int nt = 0; nt < 4; ++nt) {
            float4 w0 = wf[(nt * 2 + 0) * 32 + lane];
            float4 w1 = wf[(nt * 2 + 1) * 32 + lane];
            const float* bp[4][2] = {{&w0.x, &w0.y}, {&w0.z, &w0.w},
                                     {&w1.x, &w1.y}, {&w1.z, &w1.w}};
            #pragma unroll
            for (int ks = 0; ks < 4; ++ks) {
                uint32_t b0 = __float_as_uint(*bp[ks][0]);
                uint32_t b1 = __float_as_uint(*bp[ks][1]);
                asm volatile(
                    "mma.sync.aligned.m16n8k8.row.col.f32.tf32.tf32.f32 "
                    "{%0,%1,%2,%3}, {%4,%5,%6,%7}, {%8,%9}, {%0,%1,%2,%3};"
                    : "+f"(c_[nt][0]), "+f"(c_[nt][1]),
                      "+f"(c_[nt][2]), "+f"(c_[nt][3])
                    : "r"(A[ks][0]), "r"(A[ks][1]), "r"(A[ks][2]), "r"(A[ks][3]),
                      "r"(b0), "r"(b1));
            }
        }
    };
    auto body = [&](int k, int b, int (&idx)[4]) {
        if (k + 2 < KVOL) ld_idx(k + 2, idx);   // overwrite idx(k): consumed
        if (k < KVOL - 1) CP_WAIT1(); else CP_WAIT0();
        __syncwarp();
        compute(k, b);
        if (k + 2 < KVOL) issue_data(b, idx);   // reuse buffer b
    };

    int idx0[4], idx1[4];
    ld_idx(0, idx0); issue_data(0, idx0);       // prolog: stages 0,1 in flight
    ld_idx(1, idx1); issue_data(1, idx1);

    #pragma unroll 1
    for (int k = 0; k < KVOL - 1; k += 2) {
        body(k, 0, idx0);
        body(k + 1, 1, idx1);
    }
    body(KVOL - 1, 0, idx0);                    // k = 26

    // ---- epilogue: store pre-BN rows -------------------------------------
    int r0g = v0g + g;
    int r1g = r0g + 8;
    #pragma unroll
    for (int nt = 0; nt < 4; ++nt) {
        if (r0g < N)
            *(float2*)(out + (long long)r0g * 32 + nt * 8 + 2 * q) =
                make_float2(c_[nt][0], c_[nt][1]);
        if (r1g < N)
            *(float2*)(out + (long long)r1g * 32 + nt * 8 + 2 * q) =
                make_float2(c_[nt][2], c_[nt][3]);
    }

    // ---- BN sums (padding rows are exactly zero, safe to include) --------
    float s[8], sq[8];
    #pragma unroll
    for (int nt = 0; nt < 4; ++nt) {
        s[nt * 2 + 0] = c_[nt][0] + c_[nt][2];
        s[nt * 2 + 1] = c_[nt][1] + c_[nt][3];
        sq[nt * 2 + 0] = c_[nt][0] * c_[nt][0] + c_[nt][2] * c_[nt][2];
        sq[nt * 2 + 1] = c_[nt][1] * c_[nt][1] + c_[nt][3] * c_[nt][3];
    }
    #pragma unroll
    for (int off = 16; off >= 4; off >>= 1) {
        #pragma unroll
        for (int e = 0; e < 8; ++e) {
            s[e]  += __shfl_xor_sync(~0u, s[e], off);
            sq[e] += __shfl_xor_sync(~0u, sq[e], off);
        }
    }
    if (lane < 4) {
        #pragma unroll
        for (int nt = 0; nt < 4; ++nt) {
            int ch = nt * 8 + 2 * lane;
            s_red[w * 32 + ch]           = s[nt * 2 + 0];
            s_red[w * 32 + ch + 1]       = s[nt * 2 + 1];
            s_red[256 + w * 32 + ch]     = sq[nt * 2 + 0];
            s_red[256 + w * 32 + ch + 1] = sq[nt * 2 + 1];
        }
    }
    __syncthreads();
    if (tid < 32) {
        float ts = 0.f, tq = 0.f;
        #pragma unroll
        for (int ww = 0; ww < 8; ++ww) {
            ts += s_red[ww * 32 + tid];
            tq += s_red[256 + ww * 32 + tid];
        }
        atomicAdd(&g_sum[tid], ts);
        atomicAdd(&g_sumsq[tid], tq);
    }
}

// ---------------------------------------------------------------------------
// K4: BN (batch stats, biased var) + ReLU, in place on out
// ---------------------------------------------------------------------------
__global__ void k_bnrelu(const float* __restrict__ gamma,
                         const float* __restrict__ beta,
                         float* __restrict__ out, int N) {
    __shared__ float s_scale[32], s_shift[32];
    int tid = threadIdx.x;
    if (tid < 32) {
        float invN = 1.0f / (float)N;
        float mean = g_sum[tid] * invN;
        float var  = g_sumsq[tid] * invN - mean * mean;
        float sc   = gamma[tid] * rsqrtf(var + 1e-5f);
        s_scale[tid] = sc;
        s_shift[tid] = fmaf(-mean, sc, beta[tid]);
    }
    __syncthreads();
    long long total = (long long)N * 8;
    for (long long j = blockIdx.x * (long long)blockDim.x + tid; j < total;
         j += (long long)gridDim.x * blockDim.x) {
        int c = ((int)(j & 7)) * 4;
        float4 v = *(const float4*)(out + j * 4);
        float4 r;
        r.x = fmaxf(fmaf(v.x, s_scale[c + 0], s_shift[c + 0]), 0.f);
        r.y = fmaxf(fmaf(v.y, s_scale[c + 1], s_shift[c + 1]), 0.f);
        r.z = fmaxf(fmaf(v.z, s_scale[c + 2], s_shift[c + 2]), 0.f);
        r.w = fmaxf(fmaf(v.w, s_scale[c + 3], s_shift[c + 3]), 0.f);
        *(float4*)(out + j * 4) = r;
    }
}

// ---------------------------------------------------------------------------
// Launch. Inputs: feats, W, gamma, beta, in_idx, out_idx, mask (mask unused)
// ---------------------------------------------------------------------------
extern "C" void kernel_launch(void* const* d_in, const int* in_sizes, int n_in,
                              void* d_out, int out_size) {
    const float* feats   = (const float*)d_in[0];
    const float* W       = (const float*)d_in[1];
    const float* gamma   = (const float*)d_in[2];
    const float* beta    = (const float*)d_in[3];
    const int*   in_idx  = (const int*)d_in[4];
    const int*   out_idx = (const int*)d_in[5];
    const int N = in_sizes[0] / 32;
    float* out = (float*)d_out;

    k_init<<<1024, 256>>>(KVOL * N);
    dim3 sg((N + 255) / 256, KVOL);
    k_scatter<<<sg, 256>>>(out_idx, in_idx, N);
    k_wfrag<<<KVOL, 256>>>(W);
    k_fcvt<<<2048, 256>>>(feats, N * 32);
    k_conv_mma<<<(N + TILE_M - 1) / TILE_M, 256>>>(out, N);
    k_bnrelu<<<1024, 256>>>(gamma, beta, out, N);
}

// round 9
// speedup vs baseline: 3.4531x; 1.3073x over previous
#include <cuda_runtime.h>
#include <cuda_fp16.h>
#include <cstdint>

#define KVOL 27
#define MAXN 131072
#define TILE_M 128
#define ROWB 80   // smem bytes per 32-half row (64B data + 16B pad: conflict-free)

// ---------------------------------------------------------------------------
// Scratch (device globals — allocation rules forbid cudaMalloc)
// ---------------------------------------------------------------------------
__device__ static int      g_nbr[KVOL * MAXN];        // nbr[k][o] = in idx or -1
__device__ __align__(16) static __half   g_fh[MAXN * 32];    // feats, fp16
__device__ __align__(16) static uint32_t g_wfh[KVOL * 512];  // lane-order fp16 B frags
__device__ static float g_sum[32];
__device__ static float g_sumsq[32];

// ---------------------------------------------------------------------------
// cp.async helpers (Ampere+; legal under compute_100)
// ---------------------------------------------------------------------------
__device__ __forceinline__ uint32_t smem_u32(const void* p) {
    uint32_t a;
    asm("{ .reg .u64 t; cvta.to.shared.u64 t, %1; cvt.u32.u64 %0, t; }"
        : "=r"(a) : "l"(p));
    return a;
}
__device__ __forceinline__ void cp_async16(uint32_t dst, const void* src, int src_sz) {
    asm volatile("cp.async.ca.shared.global [%0], [%1], 16, %2;"
                 :: "r"(dst), "l"(src), "r"(src_sz) : "memory");
}
#define CP_COMMIT() asm volatile("cp.async.commit_group;" ::: "memory")
#define CP_WAIT0()  asm volatile("cp.async.wait_group 0;" ::: "memory")
#define CP_WAIT1()  asm volatile("cp.async.wait_group 1;" ::: "memory")
#define CP_WAIT2()  asm volatile("cp.async.wait_group 2;" ::: "memory")

// ---------------------------------------------------------------------------
// K0: fused setup — nbr init, feats->fp16, lane-order W fragment table.
// W fragment value for element i = koff*512 + p*128 + lane*4 + j:
//   slot s = 2p + (j>>1)  (s = nt*2 + kstep), reg r = j&1
//   o = nt*8 + (lane>>2); k0 = kstep*16 + 2*(lane&3) + (r ? 8 : 0)
//   packed half2 = ( W[koff][k0][o], W[koff][k0+1][o] )
// ---------------------------------------------------------------------------
__global__ void k_setup(const float* __restrict__ feats,
                        const float* __restrict__ W, int N) {
    int idx0 = blockIdx.x * blockDim.x + threadIdx.x;
    int stride = gridDim.x * blockDim.x;
    int n_nbr = KVOL * N, n_f = N * 32, n_w = KVOL * 512;
    for (int i = idx0; i < n_nbr; i += stride) g_nbr[i] = -1;
    for (int i = idx0; i < n_f; i += stride)
        g_fh[i] = __float2half_rn(feats[i]);
    for (int i = idx0; i < n_w; i += stride) {
        int koff = i >> 9, t = i & 511;
        int p = t >> 7, lane = (t >> 2) & 31, j = t & 3;
        int s = 2 * p + (j >> 1), r = j & 1;
        int nt = s >> 1, kstep = s & 1;
        int g = lane >> 2, q = lane & 3;
        int o = nt * 8 + g;
        int k0 = kstep * 16 + 2 * q + (r ? 8 : 0);
        __half2 hv = __halves2half2(
            __float2half_rn(W[koff * 1024 + k0 * 32 + o]),
            __float2half_rn(W[koff * 1024 + (k0 + 1) * 32 + o]));
        g_wfh[i] = *(uint32_t*)&hv;
    }
    if (idx0 < 32) { g_sum[idx0] = 0.f; g_sumsq[idx0] = 0.f; }
}

// ---------------------------------------------------------------------------
// K2: scatter kernel maps -> dense nbr table (validity from out_idx
// monotonicity: valid entries form a strictly increasing prefix per k).
// ---------------------------------------------------------------------------
__global__ void k_scatter(const int* __restrict__ out_idx,
                          const int* __restrict__ in_idx, int N) {
    int p = blockIdx.x * blockDim.x + threadIdx.x;
    int k = blockIdx.y;
    if (p >= N) return;
    long long base = (long long)k * N;
    int o = out_idx[base + p];
    bool valid = (p == 0) || (o > out_idx[base + p - 1]);
    if (valid) g_nbr[base + o] = in_idx[base + p];
}

// ---------------------------------------------------------------------------
// K3: warp-private 3-stage pipelined fp16 mma gather-GEMM.
// One CTA / 128-voxel tile, 8 warps; warp w owns rows [w*16, w*16+16).
// Per warp-k: 8 LDS.32 (A) + 4 LDG.128 (B, coalesced lane-order) + 8 MMA.
// idx for stage k+3 loaded at top of body(k), issued at bottom (cp.async).
// ZERO __syncthreads in the main loop.
// ---------------------------------------------------------------------------
__global__ __launch_bounds__(256, 2) void k_conv_mma(float* __restrict__ out, int N) {
    __shared__ __align__(16) char a_ws[8][3][16 * ROWB];  // 30720 B
    const int tid  = threadIdx.x;
    const int w    = tid >> 5;
    const int lane = tid & 31;
    const int g    = lane >> 2;
    const int q    = lane & 3;
    const int grp  = lane & 3;           // 16B group within row
    const int rr0  = lane >> 2;          // gather rows rr0, rr0+8
    const int obase = blockIdx.x * TILE_M;
    const int v0g   = obase + w * 16;    // warp's global row base

    uint32_t adst[3][2];
    #pragma unroll
    for (int b = 0; b < 3; ++b) {
        adst[b][0] = smem_u32(&a_ws[w][b][rr0 * ROWB + grp * 16]);
        adst[b][1] = smem_u32(&a_ws[w][b][(rr0 + 8) * ROWB + grp * 16]);
    }

    float c_[4][4];
    #pragma unroll
    for (int nt = 0; nt < 4; ++nt)
        c_[nt][0] = c_[nt][1] = c_[nt][2] = c_[nt][3] = 0.f;

    auto ld_idx = [&](int k, int (&idx)[2]) {
        const int* nb = g_nbr + (long long)k * N + v0g;
        int i0 = nb[rr0], i1 = nb[rr0 + 8];
        idx[0] = (v0g + rr0 < N) ? i0 : -1;
        idx[1] = (v0g + rr0 + 8 < N) ? i1 : -1;
    };
    auto issue_data = [&](int b, const int (&idx)[2]) {
        #pragma unroll
        for (int t = 0; t < 2; ++t) {
            int src = idx[t];
            const __half* gp = g_fh + (src >= 0 ? (long long)src * 32 + grp * 8 : 0);
            cp_async16(adst[b][t], gp, src >= 0 ? 16 : 0);
        }
        CP_COMMIT();
    };
    auto compute = [&](int k, int b) {
        const char* ap = a_ws[w][b];
        uint32_t A[2][4];
        #pragma unroll
        for (int ks = 0; ks < 2; ++ks) {
            int base = ks * 32 + q * 4;
            A[ks][0] = *(const uint32_t*)(ap + g * ROWB + base);
            A[ks][1] = *(const uint32_t*)(ap + (g + 8) * ROWB + base);
            A[ks][2] = *(const uint32_t*)(ap + g * ROWB + base + 16);
            A[ks][3] = *(const uint32_t*)(ap + (g + 8) * ROWB + base + 16);
        }
        const uint4* wf = (const uint4*)(g_wfh + k * 512);
        uint4 U[4];
        #pragma unroll
        for (int p = 0; p < 4; ++p) U[p] = wf[p * 32 + lane];
        #pragma unroll
        for (int nt = 0; nt < 4; ++nt) {
            #pragma unroll
            for (int ks = 0; ks < 2; ++ks) {
                int s = nt * 2 + ks, p = s >> 1;
                uint32_t b0 = (s & 1) ? U[p].z : U[p].x;
                uint32_t b1 = (s & 1) ? U[p].w : U[p].y;
                asm volatile(
                    "mma.sync.aligned.m16n8k16.row.col.f32.f16.f16.f32 "
                    "{%0,%1,%2,%3}, {%4,%5,%6,%7}, {%8,%9}, {%0,%1,%2,%3};"
                    : "+f"(c_[nt][0]), "+f"(c_[nt][1]),
                      "+f"(c_[nt][2]), "+f"(c_[nt][3])
                    : "r"(A[ks][0]), "r"(A[ks][1]), "r"(A[ks][2]), "r"(A[ks][3]),
                      "r"(b0), "r"(b1));
            }
        }
    };
    auto body = [&](int k, int b) {
        int idxn[2];
        bool have = (k + 3 < KVOL);
        if (have) ld_idx(k + 3, idxn);
        int wn = KVOL - 1 - k;
        if (wn >= 2) CP_WAIT2(); else if (wn == 1) CP_WAIT1(); else CP_WAIT0();
        __syncwarp();
        compute(k, b);
        if (have) issue_data(b, idxn);   // buffer b reused for stage k+3
    };

    // prolog: stages 0,1,2 in flight
    {
        int idx[2];
        ld_idx(0, idx); issue_data(0, idx);
        ld_idx(1, idx); issue_data(1, idx);
        ld_idx(2, idx); issue_data(2, idx);
    }
    #pragma unroll 1
    for (int k = 0; k < KVOL; k += 3) {   // 27 = 9 x 3
        body(k, 0);
        body(k + 1, 1);
        body(k + 2, 2);
    }

    // ---- epilogue: store pre-BN rows -------------------------------------
    int r0g = v0g + g;
    int r1g = r0g + 8;
    #pragma unroll
    for (int nt = 0; nt < 4; ++nt) {
        if (r0g < N)
            *(float2*)(out + (long long)r0g * 32 + nt * 8 + 2 * q) =
                make_float2(c_[nt][0], c_[nt][1]);
        if (r1g < N)
            *(float2*)(out + (long long)r1g * 32 + nt * 8 + 2 * q) =
                make_float2(c_[nt][2], c_[nt][3]);
    }

    // ---- BN sums (padding rows are exactly zero, safe to include) --------
    float s[8], sq[8];
    #pragma unroll
    for (int nt = 0; nt < 4; ++nt) {
        s[nt * 2 + 0] = c_[nt][0] + c_[nt][2];
        s[nt * 2 + 1] = c_[nt][1] + c_[nt][3];
        sq[nt * 2 + 0] = c_[nt][0] * c_[nt][0] + c_[nt][2] * c_[nt][2];
        sq[nt * 2 + 1] = c_[nt][1] * c_[nt][1] + c_[nt][3] * c_[nt][3];
    }
    #pragma unroll
    for (int off = 16; off >= 4; off >>= 1) {
        #pragma unroll
        for (int e = 0; e < 8; ++e) {
            s[e]  += __shfl_xor_sync(~0u, s[e], off);
            sq[e] += __shfl_xor_sync(~0u, sq[e], off);
        }
    }
    __syncthreads();                       // a_ws reads done; reuse as s_red
    float* s_red = (float*)&a_ws[0][0][0]; // 512 floats
    if (lane < 4) {
        #pragma unroll
        for (int nt = 0; nt < 4; ++nt) {
            int ch = nt * 8 + 2 * lane;
            s_red[w * 32 + ch]           = s[nt * 2 + 0];
            s_red[w * 32 + ch + 1]       = s[nt * 2 + 1];
            s_red[256 + w * 32 + ch]     = sq[nt * 2 + 0];
            s_red[256 + w * 32 + ch + 1] = sq[nt * 2 + 1];
        }
    }
    __syncthreads();
    if (tid < 32) {
        float ts = 0.f, tq = 0.f;
        #pragma unroll
        for (int ww = 0; ww < 8; ++ww) {
            ts += s_red[ww * 32 + tid];
            tq += s_red[256 + ww * 32 + tid];
        }
        atomicAdd(&g_sum[tid], ts);
        atomicAdd(&g_sumsq[tid], tq);
    }
}

// ---------------------------------------------------------------------------
// K4: BN (batch stats, biased var) + ReLU, in place on out
// ---------------------------------------------------------------------------
__global__ void k_bnrelu(const float* __restrict__ gamma,
                         const float* __restrict__ beta,
                         float* __restrict__ out, int N) {
    __shared__ float s_scale[32], s_shift[32];
    int tid = threadIdx.x;
    if (tid < 32) {
        float invN = 1.0f / (float)N;
        float mean = g_sum[tid] * invN;
        float var  = g_sumsq[tid] * invN - mean * mean;
        float sc   = gamma[tid] * rsqrtf(var + 1e-5f);
        s_scale[tid] = sc;
        s_shift[tid] = fmaf(-mean, sc, beta[tid]);
    }
    __syncthreads();
    long long total = (long long)N * 8;
    for (long long j = blockIdx.x * (long long)blockDim.x + tid; j < total;
         j += (long long)gridDim.x * blockDim.x) {
        int c = ((int)(j & 7)) * 4;
        float4 v = *(const float4*)(out + j * 4);
        float4 r;
        r.x = fmaxf(fmaf(v.x, s_scale[c + 0], s_shift[c + 0]), 0.f);
        r.y = fmaxf(fmaf(v.y, s_scale[c + 1], s_shift[c + 1]), 0.f);
        r.z = fmaxf(fmaf(v.z, s_scale[c + 2], s_shift[c + 2]), 0.f);
        r.w = fmaxf(fmaf(v.w, s_scale[c + 3], s_shift[c + 3]), 0.f);
        *(float4*)(out + j * 4) = r;
    }
}

// ---------------------------------------------------------------------------
// Launch. Inputs: feats, W, gamma, beta, in_idx, out_idx, mask (mask unused)
// ---------------------------------------------------------------------------
extern "C" void kernel_launch(void* const* d_in, const int* in_sizes, int n_in,
                              void* d_out, int out_size) {
    const float* feats   = (const float*)d_in[0];
    const float* W       = (const float*)d_in[1];
    const float* gamma   = (const float*)d_in[2];
    const float* beta    = (const float*)d_in[3];
    const int*   in_idx  = (const int*)d_in[4];
    const int*   out_idx = (const int*)d_in[5];
    const int N = in_sizes[0] / 32;
    float* out = (float*)d_out;

    k_setup<<<2048, 256>>>(feats, W, N);
    dim3 sg((N + 255) / 256, KVOL);
    k_scatter<<<sg, 256>>>(out_idx, in_idx, N);
    k_conv_mma<<<(N + TILE_M - 1) / TILE_M, 256>>>(out, N);
    k_bnrelu<<<1024, 256>>>(gamma, beta, out, N);
}

// round 10
// speedup vs baseline: 3.8478x; 1.1143x over previous
#include <cuda_runtime.h>
#include <cuda_fp16.h>
#include <cstdint>

#define KVOL 27
#define MAXN 131072
#define TILE_M 128
#define ROWB 80   // smem bytes per 32-half row (64B data + 16B pad: conflict-free)

// ---------------------------------------------------------------------------
// Scratch (device globals — allocation rules forbid cudaMalloc)
// ---------------------------------------------------------------------------
__device__ static int      g_nbr[KVOL * MAXN];               // nbr[k][o] = in idx or -1
__device__ __align__(16) static __half   g_fh[MAXN * 32];    // feats, fp16
__device__ __align__(16) static uint32_t g_wfh[KVOL * 512];  // lane-order fp16 B frags
__device__ static float g_sum[32];
__device__ static float g_sumsq[32];

// ---------------------------------------------------------------------------
// cp.async helpers (Ampere+; legal under compute_100)
// ---------------------------------------------------------------------------
__device__ __forceinline__ uint32_t smem_u32(const void* p) {
    uint32_t a;
    asm("{ .reg .u64 t; cvta.to.shared.u64 t, %1; cvt.u32.u64 %0, t; }"
        : "=r"(a) : "l"(p));
    return a;
}
__device__ __forceinline__ void cp_async16(uint32_t dst, const void* src, int src_sz) {
    asm volatile("cp.async.ca.shared.global [%0], [%1], 16, %2;"
                 :: "r"(dst), "l"(src), "r"(src_sz) : "memory");
}
#define CP_COMMIT() asm volatile("cp.async.commit_group;" ::: "memory")
#define CP_WAIT0()  asm volatile("cp.async.wait_group 0;" ::: "memory")
#define CP_WAIT1()  asm volatile("cp.async.wait_group 1;" ::: "memory")
#define CP_WAIT2()  asm volatile("cp.async.wait_group 2;" ::: "memory")

// ---------------------------------------------------------------------------
// K0: setup — feats->fp16, lane-order W fragment table, zero sums.
// (nbr table is fully written by the gap-fill scatter; no init pass needed.)
// ---------------------------------------------------------------------------
__global__ void k_setup(const float* __restrict__ feats,
                        const float* __restrict__ W, int N) {
    int idx0 = blockIdx.x * blockDim.x + threadIdx.x;
    int stride = gridDim.x * blockDim.x;
    int n_f = N * 32, n_w = KVOL * 512;
    for (int i = idx0; i < n_f; i += stride)
        g_fh[i] = __float2half_rn(feats[i]);
    for (int i = idx0; i < n_w; i += stride) {
        int koff = i >> 9, t = i & 511;
        int p = t >> 7, lane = (t >> 2) & 31, j = t & 3;
        int s = 2 * p + (j >> 1), r = j & 1;
        int nt = s >> 1, kstep = s & 1;
        int g = lane >> 2, q = lane & 3;
        int o = nt * 8 + g;
        int k0 = kstep * 16 + 2 * q + (r ? 8 : 0);
        __half2 hv = __halves2half2(
            __float2half_rn(W[koff * 1024 + k0 * 32 + o]),
            __float2half_rn(W[koff * 1024 + (k0 + 1) * 32 + o]));
        g_wfh[i] = *(uint32_t*)&hv;
    }
    if (idx0 < 32) { g_sum[idx0] = 0.f; g_sumsq[idx0] = 0.f; }
}

// ---------------------------------------------------------------------------
// K2: gap-fill scatter. out_idx[k] is strictly increasing over its valid
// prefix, so each valid entry writes its own nbr slot AND fills the gap of
// missing outputs before the next valid entry with -1 (head thread fills the
// head gap). Every nbr[k][0..N) slot is written exactly once -> no init pass.
// ---------------------------------------------------------------------------
__global__ void k_scatter(const int* __restrict__ out_idx,
                          const int* __restrict__ in_idx, int N) {
    int p = blockIdx.x * blockDim.x + threadIdx.x;
    int k = blockIdx.y;
    if (p >= N) return;
    long long base = (long long)k * N;
    int o = out_idx[base + p];
    bool valid = (p == 0) || (o > out_idx[base + p - 1]);
    if (!valid) return;
    int* nb = g_nbr + base;
    nb[o] = in_idx[base + p];
    int o_next = N;                       // last valid entry fills to N
    if (p + 1 < N) {
        int t = out_idx[base + p + 1];
        if (t > o) o_next = t;            // next entry valid
    }
    for (int j = o + 1; j < o_next; ++j) nb[j] = -1;
    if (p == 0)
        for (int j = 0; j < o; ++j) nb[j] = -1;
}

// ---------------------------------------------------------------------------
// K3: warp-private 3-stage pipelined fp16 mma gather-GEMM.
// NEW: the tile's whole index block (27 x 128 ints) is bulk-cp.async'd to
// smem in the prolog; in-loop index access is a broadcast LDS (no LDG on the
// critical path). Per warp-k: 2 LDS idx + 2 cp.async + 8 LDS.32 A +
// 4 LDG.128 B (L1-hot) + 8 MMA. ZERO __syncthreads in the main loop.
// ---------------------------------------------------------------------------
__global__ __launch_bounds__(256, 2) void k_conv_mma(float* __restrict__ out, int N) {
    __shared__ __align__(16) int  idx_s[KVOL * TILE_M];   // 13824 B
    __shared__ __align__(16) char a_ws[8][3][16 * ROWB];  // 30720 B
    const int tid  = threadIdx.x;
    const int w    = tid >> 5;
    const int lane = tid & 31;
    const int g    = lane >> 2;
    const int q    = lane & 3;
    const int grp  = lane & 3;           // 16B group within row
    const int rr0  = lane >> 2;          // gather rows rr0, rr0+8
    const int obase = blockIdx.x * TILE_M;
    const int v0g   = obase + w * 16;    // warp's global row base
    const bool r0ok = (v0g + rr0) < N;
    const bool r1ok = (v0g + rr0 + 8) < N;

    uint32_t adst[3][2];
    #pragma unroll
    for (int b = 0; b < 3; ++b) {
        adst[b][0] = smem_u32(&a_ws[w][b][rr0 * ROWB + grp * 16]);
        adst[b][1] = smem_u32(&a_ws[w][b][(rr0 + 8) * ROWB + grp * 16]);
    }

    float c_[4][4];
    #pragma unroll
    for (int nt = 0; nt < 4; ++nt)
        c_[nt][0] = c_[nt][1] = c_[nt][2] = c_[nt][3] = 0.f;

    // ---- prolog: bulk-load the tile's index block (27 x 512B) to smem ----
    {
        uint32_t ib = smem_u32(idx_s);
        // 864 16B chunks; chunk j: k = j>>5, c = j&31
        for (int j = tid; j < KVOL * 32; j += 256) {
            int k = j >> 5, c = j & 31;
            cp_async16(ib + j * 16, g_nbr + (long long)k * N + obase + c * 4, 16);
        }
        CP_COMMIT();
        CP_WAIT0();
        __syncthreads();
    }

    auto issue_stage = [&](int k, int b) {
        const int* ip = idx_s + k * TILE_M + w * 16;
        int s0 = r0ok ? ip[rr0] : -1;
        int s1 = r1ok ? ip[rr0 + 8] : -1;
        const __half* p0 = g_fh + (s0 >= 0 ? (long long)s0 * 32 + grp * 8 : 0);
        const __half* p1 = g_fh + (s1 >= 0 ? (long long)s1 * 32 + grp * 8 : 0);
        cp_async16(adst[b][0], p0, s0 >= 0 ? 16 : 0);
        cp_async16(adst[b][1], p1, s1 >= 0 ? 16 : 0);
        CP_COMMIT();
    };
    auto compute = [&](int k, int b) {
        const char* ap = a_ws[w][b];
        uint32_t A[2][4];
        #pragma unroll
        for (int ks = 0; ks < 2; ++ks) {
            int base = ks * 32 + q * 4;
            A[ks][0] = *(const uint32_t*)(ap + g * ROWB + base);
            A[ks][1] = *(const uint32_t*)(ap + (g + 8) * ROWB + base);
            A[ks][2] = *(const uint32_t*)(ap + g * ROWB + base + 16);
            A[ks][3] = *(const uint32_t*)(ap + (g + 8) * ROWB + base + 16);
        }
        const uint4* wf = (const uint4*)(g_wfh + k * 512);
        uint4 U[4];
        #pragma unroll
        for (int p = 0; p < 4; ++p) U[p] = wf[p * 32 + lane];
        #pragma unroll
        for (int nt = 0; nt < 4; ++nt) {
            #pragma unroll
            for (int ks = 0; ks < 2; ++ks) {
                int s = nt * 2 + ks, p = s >> 1;
                uint32_t b0 = (s & 1) ? U[p].z : U[p].x;
                uint32_t b1 = (s & 1) ? U[p].w : U[p].y;
                asm volatile(
                    "mma.sync.aligned.m16n8k16.row.col.f32.f16.f16.f32 "
                    "{%0,%1,%2,%3}, {%4,%5,%6,%7}, {%8,%9}, {%0,%1,%2,%3};"
                    : "+f"(c_[nt][0]), "+f"(c_[nt][1]),
                      "+f"(c_[nt][2]), "+f"(c_[nt][3])
                    : "r"(A[ks][0]), "r"(A[ks][1]), "r"(A[ks][2]), "r"(A[ks][3]),
                      "r"(b0), "r"(b1));
            }
        }
    };
    auto body = [&](int k, int b) {
        int wn = KVOL - 1 - k;
        if (wn >= 2) CP_WAIT2(); else if (wn == 1) CP_WAIT1(); else CP_WAIT0();
        __syncwarp();
        compute(k, b);
        if (k + 3 < KVOL) issue_stage(k + 3, b);   // buffer b reused for k+3
    };

    issue_stage(0, 0);
    issue_stage(1, 1);
    issue_stage(2, 2);

    #pragma unroll 1
    for (int k = 0; k < KVOL; k += 3) {   // 27 = 9 x 3
        body(k, 0);
        body(k + 1, 1);
        body(k + 2, 2);
    }

    // ---- epilogue: store pre-BN rows -------------------------------------
    int r0g = v0g + g;
    int r1g = r0g + 8;
    #pragma unroll
    for (int nt = 0; nt < 4; ++nt) {
        if (r0g < N)
            *(float2*)(out + (long long)r0g * 32 + nt * 8 + 2 * q) =
                make_float2(c_[nt][0], c_[nt][1]);
        if (r1g < N)
            *(float2*)(out + (long long)r1g * 32 + nt * 8 + 2 * q) =
                make_float2(c_[nt][2], c_[nt][3]);
    }

    // ---- BN sums (padding rows are exactly zero, safe to include) --------
    float s[8], sq[8];
    #pragma unroll
    for (int nt = 0; nt < 4; ++nt) {
        s[nt * 2 + 0] = c_[nt][0] + c_[nt][2];
        s[nt * 2 + 1] = c_[nt][1] + c_[nt][3];
        sq[nt * 2 + 0] = c_[nt][0] * c_[nt][0] + c_[nt][2] * c_[nt][2];
        sq[nt * 2 + 1] = c_[nt][1] * c_[nt][1] + c_[nt][3] * c_[nt][3];
    }
    #pragma unroll
    for (int off = 16; off >= 4; off >>= 1) {
        #pragma unroll
        for (int e = 0; e < 8; ++e) {
            s[e]  += __shfl_xor_sync(~0u, s[e], off);
            sq[e] += __shfl_xor_sync(~0u, sq[e], off);
        }
    }
    __syncthreads();                       // a_ws reads done; reuse as s_red
    float* s_red = (float*)&a_ws[0][0][0]; // 512 floats
    if (lane < 4) {
        #pragma unroll
        for (int nt = 0; nt < 4; ++nt) {
            int ch = nt * 8 + 2 * lane;
            s_red[w * 32 + ch]           = s[nt * 2 + 0];
            s_red[w * 32 + ch + 1]       = s[nt * 2 + 1];
            s_red[256 + w * 32 + ch]     = sq[nt * 2 + 0];
            s_red[256 + w * 32 + ch + 1] = sq[nt * 2 + 1];
        }
    }
    __syncthreads();
    if (tid < 32) {
        float ts = 0.f, tq = 0.f;
        #pragma unroll
        for (int ww = 0; ww < 8; ++ww) {
            ts += s_red[ww * 32 + tid];
            tq += s_red[256 + ww * 32 + tid];
        }
        atomicAdd(&g_sum[tid], ts);
        atomicAdd(&g_sumsq[tid], tq);
    }
}

// ---------------------------------------------------------------------------
// K4: BN (batch stats, biased var) + ReLU, in place on out
// ---------------------------------------------------------------------------
__global__ void k_bnrelu(const float* __restrict__ gamma,
                         const float* __restrict__ beta,
                         float* __restrict__ out, int N) {
    __shared__ float s_scale[32], s_shift[32];
    int tid = threadIdx.x;
    if (tid < 32) {
        float invN = 1.0f / (float)N;
        float mean = g_sum[tid] * invN;
        float var  = g_sumsq[tid] * invN - mean * mean;
        float sc   = gamma[tid] * rsqrtf(var + 1e-5f);
        s_scale[tid] = sc;
        s_shift[tid] = fmaf(-mean, sc, beta[tid]);
    }
    __syncthreads();
    long long total = (long long)N * 8;
    for (long long j = blockIdx.x * (long long)blockDim.x + tid; j < total;
         j += (long long)gridDim.x * blockDim.x) {
        int c = ((int)(j & 7)) * 4;
        float4 v = *(const float4*)(out + j * 4);
        float4 r;
        r.x = fmaxf(fmaf(v.x, s_scale[c + 0], s_shift[c + 0]), 0.f);
        r.y = fmaxf(fmaf(v.y, s_scale[c + 1], s_shift[c + 1]), 0.f);
        r.z = fmaxf(fmaf(v.z, s_scale[c + 2], s_shift[c + 2]), 0.f);
        r.w = fmaxf(fmaf(v.w, s_scale[c + 3], s_shift[c + 3]), 0.f);
        *(float4*)(out + j * 4) = r;
    }
}

// ---------------------------------------------------------------------------
// Launch. Inputs: feats, W, gamma, beta, in_idx, out_idx, mask (mask unused)
// ---------------------------------------------------------------------------
extern "C" void kernel_launch(void* const* d_in, const int* in_sizes, int n_in,
                              void* d_out, int out_size) {
    const float* feats   = (const float*)d_in[0];
    const float* W       = (const float*)d_in[1];
    const float* gamma   = (const float*)d_in[2];
    const float* beta    = (const float*)d_in[3];
    const int*   in_idx  = (const int*)d_in[4];
    const int*   out_idx = (const int*)d_in[5];
    const int N = in_sizes[0] / 32;
    float* out = (float*)d_out;

    k_setup<<<1024, 256>>>(feats, W, N);
    dim3 sg((N + 255) / 256, KVOL);
    k_scatter<<<sg, 256>>>(out_idx, in_idx, N);
    k_conv_mma<<<(N + TILE_M - 1) / TILE_M, 256>>>(out, N);
    k_bnrelu<<<1024, 256>>>(gamma, beta, out, N);
}